// round 11
// baseline (speedup 1.0000x reference)
#include <cuda_runtime.h>
#include <cuda_bf16.h>
#include <stdint.h>

// Problem constants (fixed by the dataset)
#define NN 50000
#define EE 600000
#define DD 128
#define HH 128
#define CC 40
#define LL 3
#define EPS 1e-5f

#define NPAD (((NN + 127) / 128) * 128)   // 50048 padded rows
#define SA 136                            // padded smem row stride (bf16 elems)
#define WIMG 17408                        // 128 * 136 bf16 per W image
#define WIMGP 8704                        // 64 * 136 bf16 per Wpred image
#define NWP (LL * 128 * 128)              // 49152 conv/lin wprep items
#define NWTOT (NWP + 64 * 128)            // + pred wprep items = 57344
#define PREPX (NPAD * 32)                 // 1601536 xprep items

// ---------------- scratch (static __device__, no allocation) ----------------
__device__ __align__(16) float g_hc[NN * HH];   // dinv-scaled x @ Wconv[i]
__device__ __align__(16) float g_hl[NN * HH];   // x @ Wlin[i]
__device__ __align__(16) float g_xf[NN * HH];   // JK sum (layers 0,1)
__device__ __align__(16) __nv_bfloat16 g_xh[NPAD * HH]; // hi plane
__device__ __align__(16) __nv_bfloat16 g_xl[NPAD * HH]; // lo plane
__device__ float g_dinv[NN];
__device__ int   g_cnt[NN];               // degree histogram; zeroed by k_scan1
__device__ int   g_off[NN + 1];
__device__ int   g_pos[NN];               // placement cursor = off[i]+deg[i]
__device__ int   g_part[128];
__device__ int   g_src[EE];               // CSR src indices
// Preformatted W: [layer][conv-hi, conv-lo, lin-hi, lin-lo][128n x 136k] bf16
__device__ __align__(16) __nv_bfloat16 g_wb[LL * 4 * WIMG];
// Preformatted Wpred: [hi, lo][64n x 136k] bf16 (rows 40-63 zero)
__device__ __align__(16) __nv_bfloat16 g_wbp[2 * WIMGP];

// ---------------- small PTX helpers ----------------
__device__ __forceinline__ uint32_t smem_u32(const void* p) {
    uint32_t a;
    asm("{ .reg .u64 t; cvta.to.shared.u64 t, %1; cvt.u32.u64 %0, t; }"
        : "=r"(a) : "l"(p));
    return a;
}
__device__ __forceinline__ void ldsm_x4(uint32_t* r, uint32_t addr) {
    asm volatile("ldmatrix.sync.aligned.m8n8.x4.shared.b16 {%0,%1,%2,%3}, [%4];"
        : "=r"(r[0]), "=r"(r[1]), "=r"(r[2]), "=r"(r[3]) : "r"(addr));
}
__device__ __forceinline__ void ldsm_x2(uint32_t* r, uint32_t addr) {
    asm volatile("ldmatrix.sync.aligned.m8n8.x2.shared.b16 {%0,%1}, [%2];"
        : "=r"(r[0]), "=r"(r[1]) : "r"(addr));
}
__device__ __forceinline__ void mma_bf16(float* c, const uint32_t* a,
                                         const uint32_t* b) {
    asm volatile("mma.sync.aligned.m16n8k16.row.col.f32.bf16.bf16.f32 "
                 "{%0,%1,%2,%3}, {%4,%5,%6,%7}, {%8,%9}, {%0,%1,%2,%3};"
                 : "+f"(c[0]), "+f"(c[1]), "+f"(c[2]), "+f"(c[3])
                 : "r"(a[0]), "r"(a[1]), "r"(a[2]), "r"(a[3]),
                   "r"(b[0]), "r"(b[1]));
}
__device__ __forceinline__ void cp16(uint32_t dst, const void* src) {
    asm volatile("cp.async.cg.shared.global [%0], [%1], 16;"
                 :: "r"(dst), "l"(src));
}
#define CP_COMMIT() asm volatile("cp.async.commit_group;" ::: "memory")
__device__ __forceinline__ float wredsum(float v) {
    #pragma unroll
    for (int o = 16; o > 0; o >>= 1) v += __shfl_xor_sync(0xffffffffu, v, o);
    return v;
}
__device__ __forceinline__ int wredsumi(int v) {
    #pragma unroll
    for (int o = 16; o > 0; o >>= 1) v += __shfl_xor_sync(0xffffffffu, v, o);
    return v;
}
// hi/lo bf16 split pack: low half = first value
__device__ __forceinline__ void split2(float a, float b, uint32_t &hp, uint32_t &lp) {
    __nv_bfloat16 ha = __float2bfloat16(a);
    __nv_bfloat16 hb = __float2bfloat16(b);
    __nv_bfloat16 la = __float2bfloat16(a - __bfloat162float(ha));
    __nv_bfloat16 lb = __float2bfloat16(b - __bfloat162float(hb));
    hp = (uint32_t)__bfloat16_as_ushort(ha) | ((uint32_t)__bfloat16_as_ushort(hb) << 16);
    lp = (uint32_t)__bfloat16_as_ushort(la) | ((uint32_t)__bfloat16_as_ushort(lb) << 16);
}

// ---------------- merged prep: W images + input planes + degree -------------
__global__ void k_prep(const float* __restrict__ Wconv,
                       const float* __restrict__ Wlin,
                       const float* __restrict__ Wpred,
                       const float* __restrict__ x,
                       const int* __restrict__ ei, int e, int n) {
    int i = blockIdx.x * blockDim.x + threadIdx.x;
    if (i < NWP) {
        int l = i >> 14;
        int k = (i >> 7) & 127;
        int nn = i & 127;
        float c = Wconv[l * 16384 + k * 128 + nn];
        float v = Wlin [l * 16384 + k * 128 + nn];
        int pos = nn * SA + k;
        __nv_bfloat16 ch = __float2bfloat16(c);
        __nv_bfloat16 cl = __float2bfloat16(c - __bfloat162float(ch));
        __nv_bfloat16 vh = __float2bfloat16(v);
        __nv_bfloat16 vl = __float2bfloat16(v - __bfloat162float(vh));
        __nv_bfloat16* base = g_wb + (size_t)l * 4 * WIMG;
        base[0 * WIMG + pos] = ch;
        base[1 * WIMG + pos] = cl;
        base[2 * WIMG + pos] = vh;
        base[3 * WIMG + pos] = vl;
    } else if (i < NWTOT) {
        int j = i - NWP;
        int nn = j >> 7;
        int k = j & 127;
        float v = (nn < CC) ? Wpred[k * CC + nn] : 0.f;
        __nv_bfloat16 vh = __float2bfloat16(v);
        __nv_bfloat16 vl = __float2bfloat16(v - __bfloat162float(vh));
        int pos = nn * SA + k;
        g_wbp[pos]         = vh;
        g_wbp[WIMGP + pos] = vl;
    } else if (i < NWTOT + PREPX) {
        int j = i - NWTOT;
        int row = j >> 5;
        float4 v = make_float4(0.f, 0.f, 0.f, 0.f);
        if (row < n) v = ((const float4*)x)[j];
        uint32_t h0, l0, h1, l1;
        split2(v.x, v.y, h0, l0);
        split2(v.z, v.w, h1, l1);
        ((uint2*)g_xh)[j] = make_uint2(h0, h1);
        ((uint2*)g_xl)[j] = make_uint2(l0, l1);
    } else {
        int j = i - NWTOT - PREPX;
        if (j < e) atomicAdd(&g_cnt[ei[e + j]], 1);
    }
}

// warp-shuffle block scan; also computes dinv, zeroes g_cnt, seeds g_pos
__global__ void k_scan1(int n) {
    __shared__ int ws[32];
    int t = threadIdx.x, idx = blockIdx.x * 1024 + t;
    int val = (idx < n) ? g_cnt[idx] : 0;
    if (idx < n) {
        g_dinv[idx] = rsqrtf((float)val + 1.0f);
        g_cnt[idx] = 0;
    }
    int lane = t & 31, w = t >> 5;
    int inc = val;
    #pragma unroll
    for (int o = 1; o < 32; o <<= 1) {
        int u = __shfl_up_sync(0xffffffffu, inc, o);
        if (lane >= o) inc += u;
    }
    if (lane == 31) ws[w] = inc;
    __syncthreads();
    if (w == 0) {
        int s = ws[lane];
        int sc = s;
        #pragma unroll
        for (int o = 1; o < 32; o <<= 1) {
            int u = __shfl_up_sync(0xffffffffu, sc, o);
            if (lane >= o) sc += u;
        }
        ws[lane] = sc - s;
        if (lane == 31) g_part[blockIdx.x] = sc;
    }
    __syncthreads();
    if (idx < n) {
        int excl = inc - val + ws[w];
        g_off[idx] = excl;
        g_pos[idx] = excl + val;
    }
}
__global__ void k_scan3(int n, int e) {
    __shared__ int base;
    int t = threadIdx.x;
    if (t < 32) {
        int s = 0;
        for (int j = t; j < blockIdx.x; j += 32) s += g_part[j];
        s = wredsumi(s);
        if (t == 0) base = s;
    }
    __syncthreads();
    int idx = blockIdx.x * 1024 + t;
    if (idx < n) { g_off[idx] += base; g_pos[idx] += base; }
    if (blockIdx.x == 0 && t == 0) g_off[n] = e;
}
// 2 edges per thread; slot via atomicSub on g_pos
__global__ void k_place(const int* __restrict__ ei, int e) {
    int i0 = (blockIdx.x * blockDim.x + threadIdx.x) * 2;
    if (i0 + 1 < e) {
        int2 s = *(const int2*)(ei + i0);
        int2 d = *(const int2*)(ei + e + i0);
        int p0 = atomicSub(&g_pos[d.x], 1) - 1;
        int p1 = atomicSub(&g_pos[d.y], 1) - 1;
        g_src[p0] = s.x;
        g_src[p1] = s.y;
    } else if (i0 < e) {
        int s = ei[i0];
        int d = ei[e + i0];
        int p = atomicSub(&g_pos[d], 1) - 1;
        g_src[p] = s;
    }
}

// ---------------- tensor-core GEMM: [hc' | hl] = X @ [Wconv | Wlin] ---------
// cp.async k-stage pipelined. CTA: 128 rows x 256 cols, 512 threads.
#define OFF_AL 34816
#define OFF_B  69632
#define MMA_SMEM (OFF_B + 4 * 34816)   // 208896 bytes

__global__ void __launch_bounds__(512, 1)
k_mma(int layer, int nrows) {
    extern __shared__ char smc[];
    uint32_t sb = smem_u32(smc);
    int tid = threadIdx.x;
    int lane = tid & 31;
    int wid = tid >> 5;
    int row0 = blockIdx.x * 128;
    const __nv_bfloat16* wbase = g_wb + (size_t)layer * 4 * WIMG;

    // issue one k-stage (24KB: A hi/lo slices + 4 B-image slices)
    auto issue_stage = [&](int ks) {
        #pragma unroll
        for (int c = tid; c < 1536; c += 512) {
            int p = c >> 8;          // plane 0..5
            int q = c & 255;
            int row = q >> 1;
            int half = q & 1;
            uint32_t dst;
            const char* src;
            if (p < 2) {
                dst = sb + (p ? OFF_AL : 0)
                    + (uint32_t)(row * SA + ks * 16) * 2 + half * 16;
                const __nv_bfloat16* g = p ? g_xl : g_xh;
                src = (const char*)(g + ((size_t)(row0 + row) * 128 + ks * 16))
                    + half * 16;
            } else {
                dst = sb + OFF_B + (uint32_t)(p - 2) * 34816
                    + (uint32_t)(row * SA + ks * 16) * 2 + half * 16;
                src = (const char*)(wbase + (size_t)(p - 2) * WIMG
                    + (row * SA + ks * 16)) + half * 16;
            }
            cp16(dst, src);
        }
        CP_COMMIT();
    };

    issue_stage(0);
    issue_stage(1);

    int wr  = wid >> 2;
    int wc2 = wid & 3;
    int sel = wc2 >> 1;
    int nb64 = wc2 & 1;

    int arow = wr * 32 + (lane & 7) + ((lane & 8) ? 8 : 0);
    int akof = (lane & 16) ? 8 : 0;
    uint32_t aH = sb + (uint32_t)(arow * SA + akof) * 2;
    uint32_t aL = aH + OFF_AL;

    int brow = nb64 * 64 + (lane & 7);
    int bkof = (lane & 8) ? 8 : 0;
    uint32_t bH = sb + OFF_B + (uint32_t)sel * 69632 + (uint32_t)(brow * SA + bkof) * 2;
    uint32_t bL = bH + 34816;

    float c[2][8][4];
    #pragma unroll
    for (int i = 0; i < 2; i++)
        #pragma unroll
        for (int j = 0; j < 8; j++)
            #pragma unroll
            for (int q = 0; q < 4; q++) c[i][j][q] = 0.f;

    #pragma unroll
    for (int ks = 0; ks < 8; ks++) {
        if (ks < 7) asm volatile("cp.async.wait_group 1;" ::: "memory");
        else        asm volatile("cp.async.wait_group 0;" ::: "memory");
        __syncthreads();

        uint32_t ka = ks * 32;
        uint32_t ah0[4], ah1[4], al0[4], al1[4];
        ldsm_x4(ah0, aH + ka);
        ldsm_x4(ah1, aH + ka + 16 * SA * 2);
        ldsm_x4(al0, aL + ka);
        ldsm_x4(al1, aL + ka + 16 * SA * 2);
        #pragma unroll
        for (int nt = 0; nt < 8; nt++) {
            uint32_t bh[2], bl[2];
            ldsm_x2(bh, bH + nt * (8 * SA * 2) + ka);
            ldsm_x2(bl, bL + nt * (8 * SA * 2) + ka);
            mma_bf16(c[0][nt], ah0, bh);
            mma_bf16(c[1][nt], ah1, bh);
            mma_bf16(c[0][nt], ah0, bl);
            mma_bf16(c[1][nt], ah1, bl);
            mma_bf16(c[0][nt], al0, bh);
            mma_bf16(c[1][nt], al1, bh);
        }
        if (ks + 2 < 8) issue_stage(ks + 2);
    }

    float* outp = sel ? g_hl : g_hc;
    int g  = lane >> 2;
    int tg = lane & 3;
    #pragma unroll
    for (int mt = 0; mt < 2; mt++) {
        int r0 = row0 + wr * 32 + mt * 16 + g;
        float sc0 = 1.f, sc1 = 1.f;
        if (sel == 0) {
            if (r0 < nrows)     sc0 = g_dinv[r0];
            if (r0 + 8 < nrows) sc1 = g_dinv[r0 + 8];
        }
        #pragma unroll
        for (int nt = 0; nt < 8; nt++) {
            int col = nb64 * 64 + nt * 8 + tg * 2;
            if (r0 < nrows)
                *(float2*)(outp + (size_t)r0 * 128 + col) =
                    make_float2(c[mt][nt][0] * sc0, c[mt][nt][1] * sc0);
            if (r0 + 8 < nrows)
                *(float2*)(outp + (size_t)(r0 + 8) * 128 + col) =
                    make_float2(c[mt][nt][2] * sc1, c[mt][nt][3] * sc1);
        }
    }
}

// ---------------- fused aggregate + bias + residual + LN + ReLU + JK --------
__global__ void __launch_bounds__(256)
k_agg(const float* __restrict__ bconv, const float* __restrict__ blin,
      const float* __restrict__ lng, const float* __restrict__ lnb,
      int layer, int n) {
    int gwarp = (blockIdx.x * blockDim.x + threadIdx.x) >> 5;
    if (gwarp >= n) return;
    int lane = threadIdx.x & 31;
    int node = gwarp;

    float dn = g_dinv[node];
    const float4* HC = (const float4*)g_hc;
    const float4* HL = (const float4*)g_hl;
    const int* S = g_src;

    float4 acc = make_float4(0.f, 0.f, 0.f, 0.f);
    int b = g_off[node], end = g_off[node + 1];
    int i = b;
    for (; i + 4 <= end; i += 4) {
        int s0 = S[i], s1 = S[i + 1], s2 = S[i + 2], s3 = S[i + 3];
        float4 h0 = HC[s0 * 32 + lane];
        float4 h1 = HC[s1 * 32 + lane];
        float4 h2 = HC[s2 * 32 + lane];
        float4 h3 = HC[s3 * 32 + lane];
        acc.x += (h0.x + h1.x) + (h2.x + h3.x);
        acc.y += (h0.y + h1.y) + (h2.y + h3.y);
        acc.z += (h0.z + h1.z) + (h2.z + h3.z);
        acc.w += (h0.w + h1.w) + (h2.w + h3.w);
    }
    for (; i < end; i++) {
        float4 h0 = HC[S[i] * 32 + lane];
        acc.x += h0.x; acc.y += h0.y; acc.z += h0.z; acc.w += h0.w;
    }
    float4 hs = HC[node * 32 + lane];
    acc.x += hs.x; acc.y += hs.y; acc.z += hs.z; acc.w += hs.w;

    float4 hl4 = HL[node * 32 + lane];
    float4 bc  = ((const float4*)bconv)[lane];
    float4 bl  = ((const float4*)blin)[lane];
    float v0 = acc.x * dn + bc.x + hl4.x + bl.x;
    float v1 = acc.y * dn + bc.y + hl4.y + bl.y;
    float v2 = acc.z * dn + bc.z + hl4.z + bl.z;
    float v3 = acc.w * dn + bc.w + hl4.w + bl.w;

    float mu = wredsum(v0 + v1 + v2 + v3) * (1.0f / 128.0f);
    float d0 = v0 - mu, d1 = v1 - mu, d2 = v2 - mu, d3 = v3 - mu;
    float var = wredsum(d0 * d0 + d1 * d1 + d2 * d2 + d3 * d3) * (1.0f / 128.0f);
    float inv = rsqrtf(var + EPS);

    float4 g4 = ((const float4*)lng)[lane];
    float4 b4 = ((const float4*)lnb)[lane];
    v0 = fmaxf(0.f, d0 * inv * g4.x + b4.x);
    v1 = fmaxf(0.f, d1 * inv * g4.y + b4.y);
    v2 = fmaxf(0.f, d2 * inv * g4.z + b4.z);
    v3 = fmaxf(0.f, d3 * inv * g4.w + b4.w);

    float s0 = v0, s1 = v1, s2 = v2, s3 = v3;
    float4* XF = (float4*)g_xf;
    if (layer == 0) {
        XF[node * 32 + lane] = make_float4(v0, v1, v2, v3);
    } else {
        float4 r = XF[node * 32 + lane];
        if (layer == 1) {
            r.x += v0; r.y += v1; r.z += v2; r.w += v3;
            XF[node * 32 + lane] = r;
        } else {
            s0 = r.x + v0; s1 = r.y + v1; s2 = r.z + v2; s3 = r.w + v3;
        }
    }

    uint32_t h0, l0, h1, l1;
    split2(s0, s1, h0, l0);
    split2(s2, s3, h1, l1);
    ((uint2*)g_xh)[node * 32 + lane] = make_uint2(h0, h1);
    ((uint2*)g_xl)[node * 32 + lane] = make_uint2(l0, l1);
}

// ---------------- prediction GEMM via mma: out = xf @ Wpred + bpred ---------
#define POFF_AL 34816
#define POFF_B  69632
#define PRED_SMEM (POFF_B + 2 * WIMGP * 2)   // 104448 bytes

__global__ void __launch_bounds__(256, 1)
k_predmma(const float* __restrict__ bp, float* __restrict__ out, int nrows) {
    extern __shared__ char smc[];
    uint32_t sb = smem_u32(smc);
    int tid = threadIdx.x;
    int lane = tid & 31;
    int wid = tid >> 5;
    int row0 = blockIdx.x * 128;

    {
        const uint4* src = (const uint4*)g_wbp;
        uint4* dst = (uint4*)(smc + POFF_B);
        #pragma unroll
        for (int t = tid; t < 2176; t += 256) dst[t] = src[t];
    }
    {
        const uint4* sh = (const uint4*)g_xh + (size_t)row0 * 16;
        const uint4* sl = (const uint4*)g_xl + (size_t)row0 * 16;
        #pragma unroll
        for (int t = tid; t < 4096; t += 256) {
            int plane = t >> 11, r = (t >> 4) & 127, c = t & 15;
            const uint4* src = plane ? sl : sh;
            *(uint4*)(smc + plane * POFF_AL + r * (SA * 2) + c * 16) = src[r * 16 + c];
        }
    }
    __syncthreads();

    int wr = wid >> 1;
    int wc = wid & 1;

    int arow = wr * 32 + (lane & 7) + ((lane & 8) ? 8 : 0);
    int akof = (lane & 16) ? 8 : 0;
    uint32_t aH = sb + (uint32_t)(arow * SA + akof) * 2;
    uint32_t aL = aH + POFF_AL;

    int brow = wc * 32 + (lane & 7);
    int bkof = (lane & 8) ? 8 : 0;
    uint32_t bH = sb + POFF_B + (uint32_t)(brow * SA + bkof) * 2;
    uint32_t bL = bH + WIMGP * 2;

    float c[2][4][4];
    #pragma unroll
    for (int i = 0; i < 2; i++)
        #pragma unroll
        for (int j = 0; j < 4; j++)
            #pragma unroll
            for (int q = 0; q < 4; q++) c[i][j][q] = 0.f;

    #pragma unroll
    for (int ks = 0; ks < 8; ks++) {
        uint32_t ka = ks * 32;
        uint32_t ah0[4], ah1[4], al0[4], al1[4];
        ldsm_x4(ah0, aH + ka);
        ldsm_x4(ah1, aH + ka + 16 * SA * 2);
        ldsm_x4(al0, aL + ka);
        ldsm_x4(al1, aL + ka + 16 * SA * 2);
        #pragma unroll
        for (int nt = 0; nt < 4; nt++) {
            uint32_t bh[2], bl[2];
            ldsm_x2(bh, bH + nt * (8 * SA * 2) + ka);
            ldsm_x2(bl, bL + nt * (8 * SA * 2) + ka);
            mma_bf16(c[0][nt], ah0, bh);
            mma_bf16(c[1][nt], ah1, bh);
            mma_bf16(c[0][nt], ah0, bl);
            mma_bf16(c[1][nt], ah1, bl);
            mma_bf16(c[0][nt], al0, bh);
            mma_bf16(c[1][nt], al1, bh);
        }
    }

    int g  = lane >> 2;
    int tg = lane & 3;
    #pragma unroll
    for (int mt = 0; mt < 2; mt++) {
        int r0 = row0 + wr * 32 + mt * 16 + g;
        #pragma unroll
        for (int nt = 0; nt < 4; nt++) {
            int col = wc * 32 + nt * 8 + tg * 2;
            if (col < CC) {
                float b0 = bp[col], b1 = bp[col + 1];
                if (r0 < nrows)
                    *(float2*)(out + (size_t)r0 * CC + col) =
                        make_float2(c[mt][nt][0] + b0, c[mt][nt][1] + b1);
                if (r0 + 8 < nrows)
                    *(float2*)(out + (size_t)(r0 + 8) * CC + col) =
                        make_float2(c[mt][nt][2] + b0, c[mt][nt][3] + b1);
            }
        }
    }
}

// ---------------- launch ----------------
extern "C" void kernel_launch(void* const* d_in, const int* in_sizes, int n_in,
                              void* d_out, int out_size) {
    const float* x      = (const float*)d_in[0];
    const int*   ei     = (const int*)  d_in[1];
    const float* Wconv  = (const float*)d_in[2];
    const float* bconv  = (const float*)d_in[3];
    const float* Wlin   = (const float*)d_in[4];
    const float* blin   = (const float*)d_in[5];
    const float* ln_g   = (const float*)d_in[6];
    const float* ln_b   = (const float*)d_in[7];
    const float* Wpred  = (const float*)d_in[8];
    const float* bpred  = (const float*)d_in[9];
    float* out = (float*)d_out;

    int n = in_sizes[0] / DD;     // 50000
    int e = in_sizes[1] / 2;      // 600000

    static bool attr_set = false;
    if (!attr_set) {
        cudaFuncSetAttribute(k_mma, cudaFuncAttributeMaxDynamicSharedMemorySize,
                             MMA_SMEM);
        cudaFuncSetAttribute(k_predmma, cudaFuncAttributeMaxDynamicSharedMemorySize,
                             PRED_SMEM);
        attr_set = true;
    }

    int nb = (n + 1023) / 1024;

    k_prep <<<(NWTOT + PREPX + e + 255) / 256, 256>>>(Wconv, Wlin, Wpred, x, ei, e, n);
    k_scan1<<<nb, 1024>>>(n);
    k_scan3<<<nb, 1024>>>(n, e);
    k_place<<<(e / 2 + 256) / 256, 256>>>(ei, e);

    int ntiles = (n + 127) / 128;
    for (int i = 0; i < LL; i++) {
        k_mma<<<ntiles, 512, MMA_SMEM>>>(i, n);
        k_agg<<<(n + 7) / 8, 256>>>(bconv + i * HH, blin + i * HH,
                                    ln_g + i * HH, ln_b + i * HH, i, n);
    }

    k_predmma<<<ntiles, 256, PRED_SMEM>>>(bpred, out, n);
}

// round 12
// speedup vs baseline: 1.0966x; 1.0966x over previous
#include <cuda_runtime.h>
#include <cuda_bf16.h>
#include <cuda_fp16.h>
#include <stdint.h>

// Problem constants (fixed by the dataset)
#define NN 50000
#define EE 600000
#define DD 128
#define HH 128
#define CC 40
#define LL 3
#define EPS 1e-5f

#define NPAD (((NN + 127) / 128) * 128)   // 50048 padded rows
#define SA 136                            // padded smem row stride (bf16 elems)
#define WIMG 17408                        // 128 * 136 bf16 per W image
#define WIMGP 8704                        // 64 * 136 bf16 per Wpred image
#define NWP (LL * 128 * 128)              // 49152 conv/lin wprep items
#define NWTOT (NWP + 64 * 128)            // + pred wprep items = 57344
#define PREPX (NPAD * 32)                 // xprep items

// ---------------- scratch (static __device__, no allocation) ----------------
__device__ __align__(16) __half g_hc[NN * HH];  // fp16 dinv-scaled x @ Wconv[i]
__device__ __align__(16) float g_hl[NN * HH];   // x @ Wlin[i]
__device__ __align__(16) float g_xf[NN * HH];   // JK sum (layers 0,1)
__device__ __align__(16) __nv_bfloat16 g_xh[NPAD * HH]; // hi plane
__device__ __align__(16) __nv_bfloat16 g_xl[NPAD * HH]; // lo plane
__device__ float g_dinv[NN];
__device__ int   g_cnt[NN];               // degree histogram; zeroed by k_scan1
__device__ int   g_off[NN + 1];
__device__ int   g_pos[NN];               // placement cursor = off[i]+deg[i]
__device__ int   g_part[128];
__device__ int   g_src[EE];               // CSR src indices
// Preformatted W: [layer][conv-hi, conv-lo, lin-hi, lin-lo][128n x 136k] bf16
__device__ __align__(16) __nv_bfloat16 g_wb[LL * 4 * WIMG];
// Preformatted Wpred: [hi, lo][64n x 136k] bf16 (rows 40-63 zero)
__device__ __align__(16) __nv_bfloat16 g_wbp[2 * WIMGP];

// ---------------- small PTX helpers ----------------
__device__ __forceinline__ uint32_t smem_u32(const void* p) {
    uint32_t a;
    asm("{ .reg .u64 t; cvta.to.shared.u64 t, %1; cvt.u32.u64 %0, t; }"
        : "=r"(a) : "l"(p));
    return a;
}
__device__ __forceinline__ void ldsm_x4(uint32_t* r, uint32_t addr) {
    asm volatile("ldmatrix.sync.aligned.m8n8.x4.shared.b16 {%0,%1,%2,%3}, [%4];"
        : "=r"(r[0]), "=r"(r[1]), "=r"(r[2]), "=r"(r[3]) : "r"(addr));
}
__device__ __forceinline__ void ldsm_x2(uint32_t* r, uint32_t addr) {
    asm volatile("ldmatrix.sync.aligned.m8n8.x2.shared.b16 {%0,%1}, [%2];"
        : "=r"(r[0]), "=r"(r[1]) : "r"(addr));
}
__device__ __forceinline__ void mma_bf16(float* c, const uint32_t* a,
                                         const uint32_t* b) {
    asm volatile("mma.sync.aligned.m16n8k16.row.col.f32.bf16.bf16.f32 "
                 "{%0,%1,%2,%3}, {%4,%5,%6,%7}, {%8,%9}, {%0,%1,%2,%3};"
                 : "+f"(c[0]), "+f"(c[1]), "+f"(c[2]), "+f"(c[3])
                 : "r"(a[0]), "r"(a[1]), "r"(a[2]), "r"(a[3]),
                   "r"(b[0]), "r"(b[1]));
}
__device__ __forceinline__ float wredsum(float v) {
    #pragma unroll
    for (int o = 16; o > 0; o >>= 1) v += __shfl_xor_sync(0xffffffffu, v, o);
    return v;
}
__device__ __forceinline__ int wredsumi(int v) {
    #pragma unroll
    for (int o = 16; o > 0; o >>= 1) v += __shfl_xor_sync(0xffffffffu, v, o);
    return v;
}
// hi/lo bf16 split pack: low half = first value
__device__ __forceinline__ void split2(float a, float b, uint32_t &hp, uint32_t &lp) {
    __nv_bfloat16 ha = __float2bfloat16(a);
    __nv_bfloat16 hb = __float2bfloat16(b);
    __nv_bfloat16 la = __float2bfloat16(a - __bfloat162float(ha));
    __nv_bfloat16 lb = __float2bfloat16(b - __bfloat162float(hb));
    hp = (uint32_t)__bfloat16_as_ushort(ha) | ((uint32_t)__bfloat16_as_ushort(hb) << 16);
    lp = (uint32_t)__bfloat16_as_ushort(la) | ((uint32_t)__bfloat16_as_ushort(lb) << 16);
}

// ---------------- merged prep: W images + input planes + degree -------------
__global__ void k_prep(const float* __restrict__ Wconv,
                       const float* __restrict__ Wlin,
                       const float* __restrict__ Wpred,
                       const float* __restrict__ x,
                       const int* __restrict__ ei, int e, int n) {
    int i = blockIdx.x * blockDim.x + threadIdx.x;
    if (i < NWP) {
        int l = i >> 14;
        int k = (i >> 7) & 127;
        int nn = i & 127;
        float c = Wconv[l * 16384 + k * 128 + nn];
        float v = Wlin [l * 16384 + k * 128 + nn];
        int pos = nn * SA + k;
        __nv_bfloat16 ch = __float2bfloat16(c);
        __nv_bfloat16 cl = __float2bfloat16(c - __bfloat162float(ch));
        __nv_bfloat16 vh = __float2bfloat16(v);
        __nv_bfloat16 vl = __float2bfloat16(v - __bfloat162float(vh));
        __nv_bfloat16* base = g_wb + (size_t)l * 4 * WIMG;
        base[0 * WIMG + pos] = ch;
        base[1 * WIMG + pos] = cl;
        base[2 * WIMG + pos] = vh;
        base[3 * WIMG + pos] = vl;
    } else if (i < NWTOT) {
        int j = i - NWP;
        int nn = j >> 7;
        int k = j & 127;
        float v = (nn < CC) ? Wpred[k * CC + nn] : 0.f;
        __nv_bfloat16 vh = __float2bfloat16(v);
        __nv_bfloat16 vl = __float2bfloat16(v - __bfloat162float(vh));
        int pos = nn * SA + k;
        g_wbp[pos]         = vh;
        g_wbp[WIMGP + pos] = vl;
    } else if (i < NWTOT + PREPX) {
        int j = i - NWTOT;
        int row = j >> 5;
        float4 v = make_float4(0.f, 0.f, 0.f, 0.f);
        if (row < n) v = ((const float4*)x)[j];
        uint32_t h0, l0, h1, l1;
        split2(v.x, v.y, h0, l0);
        split2(v.z, v.w, h1, l1);
        ((uint2*)g_xh)[j] = make_uint2(h0, h1);
        ((uint2*)g_xl)[j] = make_uint2(l0, l1);
    } else {
        int j = i - NWTOT - PREPX;
        if (j < e) atomicAdd(&g_cnt[ei[e + j]], 1);
    }
}

// warp-shuffle block scan; also computes dinv, zeroes g_cnt, seeds g_pos
__global__ void k_scan1(int n) {
    __shared__ int ws[32];
    int t = threadIdx.x, idx = blockIdx.x * 1024 + t;
    int val = (idx < n) ? g_cnt[idx] : 0;
    if (idx < n) {
        g_dinv[idx] = rsqrtf((float)val + 1.0f);
        g_cnt[idx] = 0;
    }
    int lane = t & 31, w = t >> 5;
    int inc = val;
    #pragma unroll
    for (int o = 1; o < 32; o <<= 1) {
        int u = __shfl_up_sync(0xffffffffu, inc, o);
        if (lane >= o) inc += u;
    }
    if (lane == 31) ws[w] = inc;
    __syncthreads();
    if (w == 0) {
        int s = ws[lane];
        int sc = s;
        #pragma unroll
        for (int o = 1; o < 32; o <<= 1) {
            int u = __shfl_up_sync(0xffffffffu, sc, o);
            if (lane >= o) sc += u;
        }
        ws[lane] = sc - s;
        if (lane == 31) g_part[blockIdx.x] = sc;
    }
    __syncthreads();
    if (idx < n) {
        int excl = inc - val + ws[w];
        g_off[idx] = excl;
        g_pos[idx] = excl + val;
    }
}
__global__ void k_scan3(int n, int e) {
    __shared__ int base;
    int t = threadIdx.x;
    if (t < 32) {
        int s = 0;
        for (int j = t; j < blockIdx.x; j += 32) s += g_part[j];
        s = wredsumi(s);
        if (t == 0) base = s;
    }
    __syncthreads();
    int idx = blockIdx.x * 1024 + t;
    if (idx < n) { g_off[idx] += base; g_pos[idx] += base; }
    if (blockIdx.x == 0 && t == 0) g_off[n] = e;
}
// slot via atomicSub on g_pos; stores only src (4 B)
__global__ void k_place(const int* __restrict__ ei, int e) {
    int i = blockIdx.x * blockDim.x + threadIdx.x;
    if (i < e) {
        int s = ei[i];
        int d = ei[e + i];
        int p = atomicSub(&g_pos[d], 1) - 1;
        g_src[p] = s;
    }
}

// ---------------- tensor-core GEMM: [hc' | hl] = X @ [Wconv | Wlin] ---------
// hc' = dinv-scaled conv product, stored fp16. CTA: 128x256, 512 threads.
#define OFF_AL 34816
#define OFF_B  69632
#define MMA_SMEM (OFF_B + 4 * 34816)   // 208896 bytes

__global__ void __launch_bounds__(512, 1)
k_mma(int layer, int nrows) {
    extern __shared__ char smc[];
    uint32_t sb = smem_u32(smc);
    int tid = threadIdx.x;
    int lane = tid & 31;
    int wid = tid >> 5;
    int row0 = blockIdx.x * 128;

    {
        const uint4* src = (const uint4*)(g_wb + (size_t)layer * 4 * WIMG);
        uint4* dst = (uint4*)(smc + OFF_B);
        #pragma unroll
        for (int t = tid; t < 8704; t += 512) dst[t] = src[t];
    }
    {
        const uint4* sh = (const uint4*)g_xh + (size_t)row0 * 16;
        const uint4* sl = (const uint4*)g_xl + (size_t)row0 * 16;
        #pragma unroll
        for (int t = tid; t < 4096; t += 512) {
            int plane = t >> 11, r = (t >> 4) & 127, c = t & 15;
            const uint4* src = plane ? sl : sh;
            *(uint4*)(smc + plane * OFF_AL + r * (SA * 2) + c * 16) = src[r * 16 + c];
        }
    }
    __syncthreads();

    int wr  = wid >> 2;
    int wc2 = wid & 3;
    int sel = wc2 >> 1;
    int nb64 = wc2 & 1;

    int arow = wr * 32 + (lane & 7) + ((lane & 8) ? 8 : 0);
    int akof = (lane & 16) ? 8 : 0;
    uint32_t aH = sb + (uint32_t)(arow * SA + akof) * 2;
    uint32_t aL = aH + OFF_AL;

    int brow = nb64 * 64 + (lane & 7);
    int bkof = (lane & 8) ? 8 : 0;
    uint32_t bH = sb + OFF_B + (uint32_t)sel * 69632 + (uint32_t)(brow * SA + bkof) * 2;
    uint32_t bL = bH + 34816;

    float c[2][8][4];
    #pragma unroll
    for (int i = 0; i < 2; i++)
        #pragma unroll
        for (int j = 0; j < 8; j++)
            #pragma unroll
            for (int q = 0; q < 4; q++) c[i][j][q] = 0.f;

    #pragma unroll
    for (int ks = 0; ks < 8; ks++) {
        uint32_t ka = ks * 32;
        uint32_t ah0[4], ah1[4], al0[4], al1[4];
        ldsm_x4(ah0, aH + ka);
        ldsm_x4(ah1, aH + ka + 16 * SA * 2);
        ldsm_x4(al0, aL + ka);
        ldsm_x4(al1, aL + ka + 16 * SA * 2);
        #pragma unroll
        for (int nt = 0; nt < 8; nt++) {
            uint32_t bh[2], bl[2];
            ldsm_x2(bh, bH + nt * (8 * SA * 2) + ka);
            ldsm_x2(bl, bL + nt * (8 * SA * 2) + ka);
            mma_bf16(c[0][nt], ah0, bh);
            mma_bf16(c[1][nt], ah1, bh);
            mma_bf16(c[0][nt], ah0, bl);
            mma_bf16(c[1][nt], ah1, bl);
            mma_bf16(c[0][nt], al0, bh);
            mma_bf16(c[1][nt], al1, bh);
        }
    }

    int g  = lane >> 2;
    int tg = lane & 3;
    #pragma unroll
    for (int mt = 0; mt < 2; mt++) {
        int r0 = row0 + wr * 32 + mt * 16 + g;
        if (sel == 0) {
            // conv product: scale by dinv[row], store fp16
            float sc0 = (r0 < nrows)     ? g_dinv[r0]     : 1.f;
            float sc1 = (r0 + 8 < nrows) ? g_dinv[r0 + 8] : 1.f;
            #pragma unroll
            for (int nt = 0; nt < 8; nt++) {
                int col = nb64 * 64 + nt * 8 + tg * 2;
                if (r0 < nrows) {
                    __half2 h = __floats2half2_rn(c[mt][nt][0] * sc0,
                                                  c[mt][nt][1] * sc0);
                    *(__half2*)(g_hc + (size_t)r0 * 128 + col) = h;
                }
                if (r0 + 8 < nrows) {
                    __half2 h = __floats2half2_rn(c[mt][nt][2] * sc1,
                                                  c[mt][nt][3] * sc1);
                    *(__half2*)(g_hc + (size_t)(r0 + 8) * 128 + col) = h;
                }
            }
        } else {
            #pragma unroll
            for (int nt = 0; nt < 8; nt++) {
                int col = nb64 * 64 + nt * 8 + tg * 2;
                if (r0 < nrows)
                    *(float2*)(g_hl + (size_t)r0 * 128 + col) =
                        make_float2(c[mt][nt][0], c[mt][nt][1]);
                if (r0 + 8 < nrows)
                    *(float2*)(g_hl + (size_t)(r0 + 8) * 128 + col) =
                        make_float2(c[mt][nt][2], c[mt][nt][3]);
            }
        }
    }
}

// ---------------- fused aggregate + bias + residual + LN + ReLU + JK --------
// conv = dn * (sum_src HC[src] + HC[node]); HC is fp16, dinv-prescaled.
__global__ void __launch_bounds__(256)
k_agg(const float* __restrict__ bconv, const float* __restrict__ blin,
      const float* __restrict__ lng, const float* __restrict__ lnb,
      int layer, int n) {
    int gwarp = (blockIdx.x * blockDim.x + threadIdx.x) >> 5;
    if (gwarp >= n) return;
    int lane = threadIdx.x & 31;
    int node = gwarp;

    float dn = g_dinv[node];
    const uint2* HC2 = (const uint2*)g_hc;   // 4 halfs per lane per row
    const float4* HL = (const float4*)g_hl;
    const int* S = g_src;

    float4 acc = make_float4(0.f, 0.f, 0.f, 0.f);
    int b = g_off[node], end = g_off[node + 1];
    int i = b;
    #define GATHER(u)                                                          \
        {                                                                      \
            float2 f0 = __half22float2(*(__half2*)&(u).x);                     \
            float2 f1 = __half22float2(*(__half2*)&(u).y);                     \
            acc.x += f0.x; acc.y += f0.y; acc.z += f1.x; acc.w += f1.y;        \
        }
    for (; i + 4 <= end; i += 4) {
        int s0 = S[i], s1 = S[i + 1], s2 = S[i + 2], s3 = S[i + 3];
        uint2 u0 = HC2[s0 * 32 + lane];
        uint2 u1 = HC2[s1 * 32 + lane];
        uint2 u2 = HC2[s2 * 32 + lane];
        uint2 u3 = HC2[s3 * 32 + lane];
        GATHER(u0) GATHER(u1) GATHER(u2) GATHER(u3)
    }
    for (; i < end; i++) {
        uint2 u0 = HC2[S[i] * 32 + lane];
        GATHER(u0)
    }
    {
        uint2 us = HC2[node * 32 + lane];    // self loop
        GATHER(us)
    }
    #undef GATHER

    float4 hl4 = HL[node * 32 + lane];
    float4 bc  = ((const float4*)bconv)[lane];
    float4 bl  = ((const float4*)blin)[lane];
    float v0 = acc.x * dn + bc.x + hl4.x + bl.x;
    float v1 = acc.y * dn + bc.y + hl4.y + bl.y;
    float v2 = acc.z * dn + bc.z + hl4.z + bl.z;
    float v3 = acc.w * dn + bc.w + hl4.w + bl.w;

    float mu = wredsum(v0 + v1 + v2 + v3) * (1.0f / 128.0f);
    float d0 = v0 - mu, d1 = v1 - mu, d2 = v2 - mu, d3 = v3 - mu;
    float var = wredsum(d0 * d0 + d1 * d1 + d2 * d2 + d3 * d3) * (1.0f / 128.0f);
    float inv = rsqrtf(var + EPS);

    float4 g4 = ((const float4*)lng)[lane];
    float4 b4 = ((const float4*)lnb)[lane];
    v0 = fmaxf(0.f, d0 * inv * g4.x + b4.x);
    v1 = fmaxf(0.f, d1 * inv * g4.y + b4.y);
    v2 = fmaxf(0.f, d2 * inv * g4.z + b4.z);
    v3 = fmaxf(0.f, d3 * inv * g4.w + b4.w);

    float s0 = v0, s1 = v1, s2 = v2, s3 = v3;
    float4* XF = (float4*)g_xf;
    if (layer == 0) {
        XF[node * 32 + lane] = make_float4(v0, v1, v2, v3);
    } else {
        float4 r = XF[node * 32 + lane];
        if (layer == 1) {
            r.x += v0; r.y += v1; r.z += v2; r.w += v3;
            XF[node * 32 + lane] = r;
        } else {
            s0 = r.x + v0; s1 = r.y + v1; s2 = r.z + v2; s3 = r.w + v3;
        }
    }

    uint32_t h0, l0, h1, l1;
    split2(s0, s1, h0, l0);
    split2(s2, s3, h1, l1);
    ((uint2*)g_xh)[node * 32 + lane] = make_uint2(h0, h1);
    ((uint2*)g_xl)[node * 32 + lane] = make_uint2(l0, l1);
}

// ---------------- prediction GEMM via mma: out = xf @ Wpred + bpred ---------
#define POFF_AL 34816
#define POFF_B  69632
#define PRED_SMEM (POFF_B + 2 * WIMGP * 2)   // 104448 bytes

__global__ void __launch_bounds__(256, 1)
k_predmma(const float* __restrict__ bp, float* __restrict__ out, int nrows) {
    extern __shared__ char smc[];
    uint32_t sb = smem_u32(smc);
    int tid = threadIdx.x;
    int lane = tid & 31;
    int wid = tid >> 5;
    int row0 = blockIdx.x * 128;

    {
        const uint4* src = (const uint4*)g_wbp;
        uint4* dst = (uint4*)(smc + POFF_B);
        #pragma unroll
        for (int t = tid; t < 2176; t += 256) dst[t] = src[t];
    }
    {
        const uint4* sh = (const uint4*)g_xh + (size_t)row0 * 16;
        const uint4* sl = (const uint4*)g_xl + (size_t)row0 * 16;
        #pragma unroll
        for (int t = tid; t < 4096; t += 256) {
            int plane = t >> 11, r = (t >> 4) & 127, c = t & 15;
            const uint4* src = plane ? sl : sh;
            *(uint4*)(smc + plane * POFF_AL + r * (SA * 2) + c * 16) = src[r * 16 + c];
        }
    }
    __syncthreads();

    int wr = wid >> 1;
    int wc = wid & 1;

    int arow = wr * 32 + (lane & 7) + ((lane & 8) ? 8 : 0);
    int akof = (lane & 16) ? 8 : 0;
    uint32_t aH = sb + (uint32_t)(arow * SA + akof) * 2;
    uint32_t aL = aH + POFF_AL;

    int brow = wc * 32 + (lane & 7);
    int bkof = (lane & 8) ? 8 : 0;
    uint32_t bH = sb + POFF_B + (uint32_t)(brow * SA + bkof) * 2;
    uint32_t bL = bH + WIMGP * 2;

    float c[2][4][4];
    #pragma unroll
    for (int i = 0; i < 2; i++)
        #pragma unroll
        for (int j = 0; j < 4; j++)
            #pragma unroll
            for (int q = 0; q < 4; q++) c[i][j][q] = 0.f;

    #pragma unroll
    for (int ks = 0; ks < 8; ks++) {
        uint32_t ka = ks * 32;
        uint32_t ah0[4], ah1[4], al0[4], al1[4];
        ldsm_x4(ah0, aH + ka);
        ldsm_x4(ah1, aH + ka + 16 * SA * 2);
        ldsm_x4(al0, aL + ka);
        ldsm_x4(al1, aL + ka + 16 * SA * 2);
        #pragma unroll
        for (int nt = 0; nt < 4; nt++) {
            uint32_t bh[2], bl[2];
            ldsm_x2(bh, bH + nt * (8 * SA * 2) + ka);
            ldsm_x2(bl, bL + nt * (8 * SA * 2) + ka);
            mma_bf16(c[0][nt], ah0, bh);
            mma_bf16(c[1][nt], ah1, bh);
            mma_bf16(c[0][nt], ah0, bl);
            mma_bf16(c[1][nt], ah1, bl);
            mma_bf16(c[0][nt], al0, bh);
            mma_bf16(c[1][nt], al1, bh);
        }
    }

    int g  = lane >> 2;
    int tg = lane & 3;
    #pragma unroll
    for (int mt = 0; mt < 2; mt++) {
        int r0 = row0 + wr * 32 + mt * 16 + g;
        #pragma unroll
        for (int nt = 0; nt < 4; nt++) {
            int col = wc * 32 + nt * 8 + tg * 2;
            if (col < CC) {
                float b0 = bp[col], b1 = bp[col + 1];
                if (r0 < nrows)
                    *(float2*)(out + (size_t)r0 * CC + col) =
                        make_float2(c[mt][nt][0] + b0, c[mt][nt][1] + b1);
                if (r0 + 8 < nrows)
                    *(float2*)(out + (size_t)(r0 + 8) * CC + col) =
                        make_float2(c[mt][nt][2] + b0, c[mt][nt][3] + b1);
            }
        }
    }
}

// ---------------- launch ----------------
extern "C" void kernel_launch(void* const* d_in, const int* in_sizes, int n_in,
                              void* d_out, int out_size) {
    const float* x      = (const float*)d_in[0];
    const int*   ei     = (const int*)  d_in[1];
    const float* Wconv  = (const float*)d_in[2];
    const float* bconv  = (const float*)d_in[3];
    const float* Wlin   = (const float*)d_in[4];
    const float* blin   = (const float*)d_in[5];
    const float* ln_g   = (const float*)d_in[6];
    const float* ln_b   = (const float*)d_in[7];
    const float* Wpred  = (const float*)d_in[8];
    const float* bpred  = (const float*)d_in[9];
    float* out = (float*)d_out;

    int n = in_sizes[0] / DD;     // 50000
    int e = in_sizes[1] / 2;      // 600000

    static bool attr_set = false;
    if (!attr_set) {
        cudaFuncSetAttribute(k_mma, cudaFuncAttributeMaxDynamicSharedMemorySize,
                             MMA_SMEM);
        cudaFuncSetAttribute(k_predmma, cudaFuncAttributeMaxDynamicSharedMemorySize,
                             PRED_SMEM);
        attr_set = true;
    }

    int nb = (n + 1023) / 1024;

    k_prep <<<(NWTOT + PREPX + e + 255) / 256, 256>>>(Wconv, Wlin, Wpred, x, ei, e, n);
    k_scan1<<<nb, 1024>>>(n);
    k_scan3<<<nb, 1024>>>(n, e);
    k_place<<<(e + 255) / 256, 256>>>(ei, e);

    int ntiles = (n + 127) / 128;
    for (int i = 0; i < LL; i++) {
        k_mma<<<ntiles, 512, MMA_SMEM>>>(i, n);
        k_agg<<<(n + 7) / 8, 256>>>(bconv + i * HH, blin + i * HH,
                                    ln_g + i * HH, ln_b + i * HH, i, n);
    }

    k_predmma<<<ntiles, 256, PRED_SMEM>>>(bpred, out, n);
}

// round 13
// speedup vs baseline: 1.1188x; 1.0203x over previous
#include <cuda_runtime.h>
#include <cuda_bf16.h>
#include <cuda_fp16.h>
#include <stdint.h>

// Problem constants (fixed by the dataset)
#define NN 50000
#define EE 600000
#define DD 128
#define HH 128
#define CC 40
#define LL 3
#define EPS 1e-5f

#define NPAD (((NN + 127) / 128) * 128)   // 50048 padded rows
#define SA 136                            // padded smem row stride (bf16 elems)
#define WIMG 17408                        // 128 * 136 bf16 per W image
#define WIMGP 8704                        // 64 * 136 bf16 per Wpred image
#define NWP (LL * 128 * 128)              // 49152 conv/lin wprep items
#define NWTOT (NWP + 64 * 128)            // + pred wprep items = 57344
#define PREPX (NPAD * 32)                 // xprep items

// ---------------- scratch (static __device__, no allocation) ----------------
__device__ __align__(16) __half g_hc[NN * HH];  // fp16 dinv-scaled x @ Wconv[i]
__device__ __align__(16) __half g_hl[NN * HH];  // fp16 x @ Wlin[i]
__device__ __align__(16) float g_xf[NN * HH];   // JK sum (layers 0,1)
__device__ __align__(16) __nv_bfloat16 g_xh[NPAD * HH]; // hi plane
__device__ __align__(16) __nv_bfloat16 g_xl[NPAD * HH]; // lo plane
__device__ float g_dinv[NN];
__device__ int   g_cnt[NN];               // degree histogram; zeroed by k_scan1
__device__ int   g_off[NN + 1];
__device__ int   g_pos[NN];               // placement cursor = off[i]+deg[i]
__device__ int   g_part[128];
__device__ int   g_src[EE];               // CSR src indices
// Preformatted W: [layer][conv-hi, conv-lo, lin-hi, lin-lo][128n x 136k] bf16
__device__ __align__(16) __nv_bfloat16 g_wb[LL * 4 * WIMG];
// Preformatted Wpred: [hi, lo][64n x 136k] bf16 (rows 40-63 zero)
__device__ __align__(16) __nv_bfloat16 g_wbp[2 * WIMGP];

// ---------------- small PTX helpers ----------------
__device__ __forceinline__ uint32_t smem_u32(const void* p) {
    uint32_t a;
    asm("{ .reg .u64 t; cvta.to.shared.u64 t, %1; cvt.u32.u64 %0, t; }"
        : "=r"(a) : "l"(p));
    return a;
}
__device__ __forceinline__ void ldsm_x4(uint32_t* r, uint32_t addr) {
    asm volatile("ldmatrix.sync.aligned.m8n8.x4.shared.b16 {%0,%1,%2,%3}, [%4];"
        : "=r"(r[0]), "=r"(r[1]), "=r"(r[2]), "=r"(r[3]) : "r"(addr));
}
__device__ __forceinline__ void ldsm_x2(uint32_t* r, uint32_t addr) {
    asm volatile("ldmatrix.sync.aligned.m8n8.x2.shared.b16 {%0,%1}, [%2];"
        : "=r"(r[0]), "=r"(r[1]) : "r"(addr));
}
__device__ __forceinline__ void mma_bf16(float* c, const uint32_t* a,
                                         const uint32_t* b) {
    asm volatile("mma.sync.aligned.m16n8k16.row.col.f32.bf16.bf16.f32 "
                 "{%0,%1,%2,%3}, {%4,%5,%6,%7}, {%8,%9}, {%0,%1,%2,%3};"
                 : "+f"(c[0]), "+f"(c[1]), "+f"(c[2]), "+f"(c[3])
                 : "r"(a[0]), "r"(a[1]), "r"(a[2]), "r"(a[3]),
                   "r"(b[0]), "r"(b[1]));
}
__device__ __forceinline__ float wredsum(float v) {
    #pragma unroll
    for (int o = 16; o > 0; o >>= 1) v += __shfl_xor_sync(0xffffffffu, v, o);
    return v;
}
__device__ __forceinline__ int wredsumi(int v) {
    #pragma unroll
    for (int o = 16; o > 0; o >>= 1) v += __shfl_xor_sync(0xffffffffu, v, o);
    return v;
}
// hi/lo bf16 split pack: low half = first value
__device__ __forceinline__ void split2(float a, float b, uint32_t &hp, uint32_t &lp) {
    __nv_bfloat16 ha = __float2bfloat16(a);
    __nv_bfloat16 hb = __float2bfloat16(b);
    __nv_bfloat16 la = __float2bfloat16(a - __bfloat162float(ha));
    __nv_bfloat16 lb = __float2bfloat16(b - __bfloat162float(hb));
    hp = (uint32_t)__bfloat16_as_ushort(ha) | ((uint32_t)__bfloat16_as_ushort(hb) << 16);
    lp = (uint32_t)__bfloat16_as_ushort(la) | ((uint32_t)__bfloat16_as_ushort(lb) << 16);
}

// ---------------- merged prep: W images + input planes + degree -------------
__global__ void k_prep(const float* __restrict__ Wconv,
                       const float* __restrict__ Wlin,
                       const float* __restrict__ Wpred,
                       const float* __restrict__ x,
                       const int* __restrict__ ei, int e, int n) {
    int i = blockIdx.x * blockDim.x + threadIdx.x;
    if (i < NWP) {
        int l = i >> 14;
        int k = (i >> 7) & 127;
        int nn = i & 127;
        float c = Wconv[l * 16384 + k * 128 + nn];
        float v = Wlin [l * 16384 + k * 128 + nn];
        int pos = nn * SA + k;
        __nv_bfloat16 ch = __float2bfloat16(c);
        __nv_bfloat16 cl = __float2bfloat16(c - __bfloat162float(ch));
        __nv_bfloat16 vh = __float2bfloat16(v);
        __nv_bfloat16 vl = __float2bfloat16(v - __bfloat162float(vh));
        __nv_bfloat16* base = g_wb + (size_t)l * 4 * WIMG;
        base[0 * WIMG + pos] = ch;
        base[1 * WIMG + pos] = cl;
        base[2 * WIMG + pos] = vh;
        base[3 * WIMG + pos] = vl;
    } else if (i < NWTOT) {
        int j = i - NWP;
        int nn = j >> 7;
        int k = j & 127;
        float v = (nn < CC) ? Wpred[k * CC + nn] : 0.f;
        __nv_bfloat16 vh = __float2bfloat16(v);
        __nv_bfloat16 vl = __float2bfloat16(v - __bfloat162float(vh));
        int pos = nn * SA + k;
        g_wbp[pos]         = vh;
        g_wbp[WIMGP + pos] = vl;
    } else if (i < NWTOT + PREPX) {
        int j = i - NWTOT;
        int row = j >> 5;
        float4 v = make_float4(0.f, 0.f, 0.f, 0.f);
        if (row < n) v = ((const float4*)x)[j];
        uint32_t h0, l0, h1, l1;
        split2(v.x, v.y, h0, l0);
        split2(v.z, v.w, h1, l1);
        ((uint2*)g_xh)[j] = make_uint2(h0, h1);
        ((uint2*)g_xl)[j] = make_uint2(l0, l1);
    } else {
        int j = i - NWTOT - PREPX;
        if (j < e) atomicAdd(&g_cnt[ei[e + j]], 1);
    }
}

// warp-shuffle block scan; also computes dinv, zeroes g_cnt, seeds g_pos
__global__ void k_scan1(int n) {
    __shared__ int ws[32];
    int t = threadIdx.x, idx = blockIdx.x * 1024 + t;
    int val = (idx < n) ? g_cnt[idx] : 0;
    if (idx < n) {
        g_dinv[idx] = rsqrtf((float)val + 1.0f);
        g_cnt[idx] = 0;
    }
    int lane = t & 31, w = t >> 5;
    int inc = val;
    #pragma unroll
    for (int o = 1; o < 32; o <<= 1) {
        int u = __shfl_up_sync(0xffffffffu, inc, o);
        if (lane >= o) inc += u;
    }
    if (lane == 31) ws[w] = inc;
    __syncthreads();
    if (w == 0) {
        int s = ws[lane];
        int sc = s;
        #pragma unroll
        for (int o = 1; o < 32; o <<= 1) {
            int u = __shfl_up_sync(0xffffffffu, sc, o);
            if (lane >= o) sc += u;
        }
        ws[lane] = sc - s;
        if (lane == 31) g_part[blockIdx.x] = sc;
    }
    __syncthreads();
    if (idx < n) {
        int excl = inc - val + ws[w];
        g_off[idx] = excl;
        g_pos[idx] = excl + val;
    }
}
__global__ void k_scan3(int n, int e) {
    __shared__ int base;
    int t = threadIdx.x;
    if (t < 32) {
        int s = 0;
        for (int j = t; j < blockIdx.x; j += 32) s += g_part[j];
        s = wredsumi(s);
        if (t == 0) base = s;
    }
    __syncthreads();
    int idx = blockIdx.x * 1024 + t;
    if (idx < n) { g_off[idx] += base; g_pos[idx] += base; }
    if (blockIdx.x == 0 && t == 0) g_off[n] = e;
}
// slot via atomicSub on g_pos; stores only src (4 B)
__global__ void k_place(const int* __restrict__ ei, int e) {
    int i = blockIdx.x * blockDim.x + threadIdx.x;
    if (i < e) {
        int s = ei[i];
        int d = ei[e + i];
        int p = atomicSub(&g_pos[d], 1) - 1;
        g_src[p] = s;
    }
}

// ---------------- tensor-core GEMM: [hc' | hl] = X @ [Wconv | Wlin] ---------
// hc' = dinv-scaled conv product (fp16); hl = lin product (fp16).
// CTA: 128x256, 512 threads.
#define OFF_AL 34816
#define OFF_B  69632
#define MMA_SMEM (OFF_B + 4 * 34816)   // 208896 bytes

__global__ void __launch_bounds__(512, 1)
k_mma(int layer, int nrows) {
    extern __shared__ char smc[];
    uint32_t sb = smem_u32(smc);
    int tid = threadIdx.x;
    int lane = tid & 31;
    int wid = tid >> 5;
    int row0 = blockIdx.x * 128;

    {
        const uint4* src = (const uint4*)(g_wb + (size_t)layer * 4 * WIMG);
        uint4* dst = (uint4*)(smc + OFF_B);
        #pragma unroll
        for (int t = tid; t < 8704; t += 512) dst[t] = src[t];
    }
    {
        const uint4* sh = (const uint4*)g_xh + (size_t)row0 * 16;
        const uint4* sl = (const uint4*)g_xl + (size_t)row0 * 16;
        #pragma unroll
        for (int t = tid; t < 4096; t += 512) {
            int plane = t >> 11, r = (t >> 4) & 127, c = t & 15;
            const uint4* src = plane ? sl : sh;
            *(uint4*)(smc + plane * OFF_AL + r * (SA * 2) + c * 16) = src[r * 16 + c];
        }
    }
    __syncthreads();

    int wr  = wid >> 2;
    int wc2 = wid & 3;
    int sel = wc2 >> 1;
    int nb64 = wc2 & 1;

    int arow = wr * 32 + (lane & 7) + ((lane & 8) ? 8 : 0);
    int akof = (lane & 16) ? 8 : 0;
    uint32_t aH = sb + (uint32_t)(arow * SA + akof) * 2;
    uint32_t aL = aH + OFF_AL;

    int brow = nb64 * 64 + (lane & 7);
    int bkof = (lane & 8) ? 8 : 0;
    uint32_t bH = sb + OFF_B + (uint32_t)sel * 69632 + (uint32_t)(brow * SA + bkof) * 2;
    uint32_t bL = bH + 34816;

    float c[2][8][4];
    #pragma unroll
    for (int i = 0; i < 2; i++)
        #pragma unroll
        for (int j = 0; j < 8; j++)
            #pragma unroll
            for (int q = 0; q < 4; q++) c[i][j][q] = 0.f;

    #pragma unroll
    for (int ks = 0; ks < 8; ks++) {
        uint32_t ka = ks * 32;
        uint32_t ah0[4], ah1[4], al0[4], al1[4];
        ldsm_x4(ah0, aH + ka);
        ldsm_x4(ah1, aH + ka + 16 * SA * 2);
        ldsm_x4(al0, aL + ka);
        ldsm_x4(al1, aL + ka + 16 * SA * 2);
        #pragma unroll
        for (int nt = 0; nt < 8; nt++) {
            uint32_t bh[2], bl[2];
            ldsm_x2(bh, bH + nt * (8 * SA * 2) + ka);
            ldsm_x2(bl, bL + nt * (8 * SA * 2) + ka);
            mma_bf16(c[0][nt], ah0, bh);
            mma_bf16(c[1][nt], ah1, bh);
            mma_bf16(c[0][nt], ah0, bl);
            mma_bf16(c[1][nt], ah1, bl);
            mma_bf16(c[0][nt], al0, bh);
            mma_bf16(c[1][nt], al1, bh);
        }
    }

    int g  = lane >> 2;
    int tg = lane & 3;
    __half* outp = sel ? g_hl : g_hc;
    #pragma unroll
    for (int mt = 0; mt < 2; mt++) {
        int r0 = row0 + wr * 32 + mt * 16 + g;
        float sc0 = 1.f, sc1 = 1.f;
        if (sel == 0) {
            if (r0 < nrows)     sc0 = g_dinv[r0];
            if (r0 + 8 < nrows) sc1 = g_dinv[r0 + 8];
        }
        #pragma unroll
        for (int nt = 0; nt < 8; nt++) {
            int col = nb64 * 64 + nt * 8 + tg * 2;
            if (r0 < nrows) {
                __half2 h = __floats2half2_rn(c[mt][nt][0] * sc0,
                                              c[mt][nt][1] * sc0);
                *(__half2*)(outp + (size_t)r0 * 128 + col) = h;
            }
            if (r0 + 8 < nrows) {
                __half2 h = __floats2half2_rn(c[mt][nt][2] * sc1,
                                              c[mt][nt][3] * sc1);
                *(__half2*)(outp + (size_t)(r0 + 8) * 128 + col) = h;
            }
        }
    }
}

// ---------------- fused aggregate + bias + residual + LN + ReLU + JK --------
// conv = dn * (sum_src HC[src] + HC[node]); HC, HL fp16.
__global__ void __launch_bounds__(256)
k_agg(const float* __restrict__ bconv, const float* __restrict__ blin,
      const float* __restrict__ lng, const float* __restrict__ lnb,
      int layer, int n) {
    int gwarp = (blockIdx.x * blockDim.x + threadIdx.x) >> 5;
    if (gwarp >= n) return;
    int lane = threadIdx.x & 31;
    int node = gwarp;

    float dn = g_dinv[node];
    const uint2* HC2 = (const uint2*)g_hc;   // 4 halfs per lane per row
    const uint2* HL2 = (const uint2*)g_hl;
    const int* S = g_src;

    float4 acc = make_float4(0.f, 0.f, 0.f, 0.f);
    int b = g_off[node], end = g_off[node + 1];
    int i = b;
    #define GATHER(u)                                                          \
        {                                                                      \
            float2 f0 = __half22float2(*(__half2*)&(u).x);                     \
            float2 f1 = __half22float2(*(__half2*)&(u).y);                     \
            acc.x += f0.x; acc.y += f0.y; acc.z += f1.x; acc.w += f1.y;        \
        }
    for (; i + 4 <= end; i += 4) {
        int s0 = S[i], s1 = S[i + 1], s2 = S[i + 2], s3 = S[i + 3];
        uint2 u0 = HC2[s0 * 32 + lane];
        uint2 u1 = HC2[s1 * 32 + lane];
        uint2 u2 = HC2[s2 * 32 + lane];
        uint2 u3 = HC2[s3 * 32 + lane];
        GATHER(u0) GATHER(u1) GATHER(u2) GATHER(u3)
    }
    for (; i < end; i++) {
        uint2 u0 = HC2[S[i] * 32 + lane];
        GATHER(u0)
    }
    {
        uint2 us = HC2[node * 32 + lane];    // self loop
        GATHER(us)
    }
    #undef GATHER

    uint2 ul = HL2[node * 32 + lane];
    float2 hl0 = __half22float2(*(__half2*)&ul.x);
    float2 hl1 = __half22float2(*(__half2*)&ul.y);
    float4 bc  = ((const float4*)bconv)[lane];
    float4 bl  = ((const float4*)blin)[lane];
    float v0 = acc.x * dn + bc.x + hl0.x + bl.x;
    float v1 = acc.y * dn + bc.y + hl0.y + bl.y;
    float v2 = acc.z * dn + bc.z + hl1.x + bl.z;
    float v3 = acc.w * dn + bc.w + hl1.y + bl.w;

    float mu = wredsum(v0 + v1 + v2 + v3) * (1.0f / 128.0f);
    float d0 = v0 - mu, d1 = v1 - mu, d2 = v2 - mu, d3 = v3 - mu;
    float var = wredsum(d0 * d0 + d1 * d1 + d2 * d2 + d3 * d3) * (1.0f / 128.0f);
    float inv = rsqrtf(var + EPS);

    float4 g4 = ((const float4*)lng)[lane];
    float4 b4 = ((const float4*)lnb)[lane];
    v0 = fmaxf(0.f, d0 * inv * g4.x + b4.x);
    v1 = fmaxf(0.f, d1 * inv * g4.y + b4.y);
    v2 = fmaxf(0.f, d2 * inv * g4.z + b4.z);
    v3 = fmaxf(0.f, d3 * inv * g4.w + b4.w);

    float s0 = v0, s1 = v1, s2 = v2, s3 = v3;
    float4* XF = (float4*)g_xf;
    if (layer == 0) {
        XF[node * 32 + lane] = make_float4(v0, v1, v2, v3);
    } else {
        float4 r = XF[node * 32 + lane];
        if (layer == 1) {
            r.x += v0; r.y += v1; r.z += v2; r.w += v3;
            XF[node * 32 + lane] = r;
        } else {
            s0 = r.x + v0; s1 = r.y + v1; s2 = r.z + v2; s3 = r.w + v3;
        }
    }

    uint32_t h0, l0, h1, l1;
    split2(s0, s1, h0, l0);
    split2(s2, s3, h1, l1);
    ((uint2*)g_xh)[node * 32 + lane] = make_uint2(h0, h1);
    ((uint2*)g_xl)[node * 32 + lane] = make_uint2(l0, l1);
}

// ---------------- prediction GEMM via mma: out = xf @ Wpred + bpred ---------
#define POFF_AL 34816
#define POFF_B  69632
#define PRED_SMEM (POFF_B + 2 * WIMGP * 2)   // 104448 bytes

__global__ void __launch_bounds__(256, 1)
k_predmma(const float* __restrict__ bp, float* __restrict__ out, int nrows) {
    extern __shared__ char smc[];
    uint32_t sb = smem_u32(smc);
    int tid = threadIdx.x;
    int lane = tid & 31;
    int wid = tid >> 5;
    int row0 = blockIdx.x * 128;

    {
        const uint4* src = (const uint4*)g_wbp;
        uint4* dst = (uint4*)(smc + POFF_B);
        #pragma unroll
        for (int t = tid; t < 2176; t += 256) dst[t] = src[t];
    }
    {
        const uint4* sh = (const uint4*)g_xh + (size_t)row0 * 16;
        const uint4* sl = (const uint4*)g_xl + (size_t)row0 * 16;
        #pragma unroll
        for (int t = tid; t < 4096; t += 256) {
            int plane = t >> 11, r = (t >> 4) & 127, c = t & 15;
            const uint4* src = plane ? sl : sh;
            *(uint4*)(smc + plane * POFF_AL + r * (SA * 2) + c * 16) = src[r * 16 + c];
        }
    }
    __syncthreads();

    int wr = wid >> 1;
    int wc = wid & 1;

    int arow = wr * 32 + (lane & 7) + ((lane & 8) ? 8 : 0);
    int akof = (lane & 16) ? 8 : 0;
    uint32_t aH = sb + (uint32_t)(arow * SA + akof) * 2;
    uint32_t aL = aH + POFF_AL;

    int brow = wc * 32 + (lane & 7);
    int bkof = (lane & 8) ? 8 : 0;
    uint32_t bH = sb + POFF_B + (uint32_t)(brow * SA + bkof) * 2;
    uint32_t bL = bH + WIMGP * 2;

    float c[2][4][4];
    #pragma unroll
    for (int i = 0; i < 2; i++)
        #pragma unroll
        for (int j = 0; j < 4; j++)
            #pragma unroll
            for (int q = 0; q < 4; q++) c[i][j][q] = 0.f;

    #pragma unroll
    for (int ks = 0; ks < 8; ks++) {
        uint32_t ka = ks * 32;
        uint32_t ah0[4], ah1[4], al0[4], al1[4];
        ldsm_x4(ah0, aH + ka);
        ldsm_x4(ah1, aH + ka + 16 * SA * 2);
        ldsm_x4(al0, aL + ka);
        ldsm_x4(al1, aL + ka + 16 * SA * 2);
        #pragma unroll
        for (int nt = 0; nt < 4; nt++) {
            uint32_t bh[2], bl[2];
            ldsm_x2(bh, bH + nt * (8 * SA * 2) + ka);
            ldsm_x2(bl, bL + nt * (8 * SA * 2) + ka);
            mma_bf16(c[0][nt], ah0, bh);
            mma_bf16(c[1][nt], ah1, bh);
            mma_bf16(c[0][nt], ah0, bl);
            mma_bf16(c[1][nt], ah1, bl);
            mma_bf16(c[0][nt], al0, bh);
            mma_bf16(c[1][nt], al1, bh);
        }
    }

    int g  = lane >> 2;
    int tg = lane & 3;
    #pragma unroll
    for (int mt = 0; mt < 2; mt++) {
        int r0 = row0 + wr * 32 + mt * 16 + g;
        #pragma unroll
        for (int nt = 0; nt < 4; nt++) {
            int col = wc * 32 + nt * 8 + tg * 2;
            if (col < CC) {
                float b0 = bp[col], b1 = bp[col + 1];
                if (r0 < nrows)
                    *(float2*)(out + (size_t)r0 * CC + col) =
                        make_float2(c[mt][nt][0] + b0, c[mt][nt][1] + b1);
                if (r0 + 8 < nrows)
                    *(float2*)(out + (size_t)(r0 + 8) * CC + col) =
                        make_float2(c[mt][nt][2] + b0, c[mt][nt][3] + b1);
            }
        }
    }
}

// ---------------- launch ----------------
extern "C" void kernel_launch(void* const* d_in, const int* in_sizes, int n_in,
                              void* d_out, int out_size) {
    const float* x      = (const float*)d_in[0];
    const int*   ei     = (const int*)  d_in[1];
    const float* Wconv  = (const float*)d_in[2];
    const float* bconv  = (const float*)d_in[3];
    const float* Wlin   = (const float*)d_in[4];
    const float* blin   = (const float*)d_in[5];
    const float* ln_g   = (const float*)d_in[6];
    const float* ln_b   = (const float*)d_in[7];
    const float* Wpred  = (const float*)d_in[8];
    const float* bpred  = (const float*)d_in[9];
    float* out = (float*)d_out;

    int n = in_sizes[0] / DD;     // 50000
    int e = in_sizes[1] / 2;      // 600000

    static bool attr_set = false;
    if (!attr_set) {
        cudaFuncSetAttribute(k_mma, cudaFuncAttributeMaxDynamicSharedMemorySize,
                             MMA_SMEM);
        cudaFuncSetAttribute(k_predmma, cudaFuncAttributeMaxDynamicSharedMemorySize,
                             PRED_SMEM);
        attr_set = true;
    }

    int nb = (n + 1023) / 1024;

    k_prep <<<(NWTOT + PREPX + e + 255) / 256, 256>>>(Wconv, Wlin, Wpred, x, ei, e, n);
    k_scan1<<<nb, 1024>>>(n);
    k_scan3<<<nb, 1024>>>(n, e);
    k_place<<<(e + 255) / 256, 256>>>(ei, e);

    int ntiles = (n + 127) / 128;
    for (int i = 0; i < LL; i++) {
        k_mma<<<ntiles, 512, MMA_SMEM>>>(i, n);
        k_agg<<<(n + 7) / 8, 256>>>(bconv + i * HH, blin + i * HH,
                                    ln_g + i * HH, ln_b + i * HH, i, n);
    }

    k_predmma<<<ntiles, 256, PRED_SMEM>>>(bpred, out, n);
}

// round 14
// speedup vs baseline: 1.1401x; 1.0190x over previous
#include <cuda_runtime.h>
#include <cuda_bf16.h>
#include <cuda_fp16.h>
#include <stdint.h>

// Problem constants (fixed by the dataset)
#define NN 50000
#define EE 600000
#define DD 128
#define HH 128
#define CC 40
#define LL 3
#define EPS 1e-5f

#define NPAD (((NN + 127) / 128) * 128)   // 50048 padded rows
#define SA 136                            // padded smem row stride (bf16 elems)
#define WIMG 17408                        // 128 * 136 bf16 per W image
#define WIMGP 8704                        // 64 * 136 bf16 per Wpred image
#define NWP (LL * 128 * 128)              // 49152 conv/lin wprep items
#define NWTOT (NWP + 64 * 128)            // + pred wprep items = 57344
#define PREPX (NPAD * 32)                 // xprep items

// ---------------- scratch (static __device__, no allocation) ----------------
__device__ __align__(16) __half g_hc[NN * HH];  // fp16 dinv-scaled x @ Wconv[i]
__device__ __align__(16) __half g_hl[NN * HH];  // fp16 x @ Wlin[i]
__device__ __align__(16) float g_xf[NN * HH];   // JK sum (layers 0,1)
__device__ __align__(16) __nv_bfloat16 g_xh[NPAD * HH]; // hi plane
__device__ __align__(16) __nv_bfloat16 g_xl[NPAD * HH]; // lo plane
__device__ float g_dinv[NN];
__device__ int   g_cnt[NN];               // degree histogram; zeroed by k_scan1
__device__ int   g_off[NN + 1];
__device__ int   g_rank[EE];              // per-edge rank among same-dst edges
__device__ int   g_part[128];
__device__ int   g_src[EE];               // CSR src indices
// Preformatted W: [layer][conv-hi, conv-lo, lin-hi, lin-lo][128n x 136k] bf16
__device__ __align__(16) __nv_bfloat16 g_wb[LL * 4 * WIMG];
// Preformatted Wpred: [hi, lo][64n x 136k] bf16 (rows 40-63 zero)
__device__ __align__(16) __nv_bfloat16 g_wbp[2 * WIMGP];

// ---------------- small PTX helpers ----------------
__device__ __forceinline__ uint32_t smem_u32(const void* p) {
    uint32_t a;
    asm("{ .reg .u64 t; cvta.to.shared.u64 t, %1; cvt.u32.u64 %0, t; }"
        : "=r"(a) : "l"(p));
    return a;
}
__device__ __forceinline__ void ldsm_x4(uint32_t* r, uint32_t addr) {
    asm volatile("ldmatrix.sync.aligned.m8n8.x4.shared.b16 {%0,%1,%2,%3}, [%4];"
        : "=r"(r[0]), "=r"(r[1]), "=r"(r[2]), "=r"(r[3]) : "r"(addr));
}
__device__ __forceinline__ void ldsm_x2(uint32_t* r, uint32_t addr) {
    asm volatile("ldmatrix.sync.aligned.m8n8.x2.shared.b16 {%0,%1}, [%2];"
        : "=r"(r[0]), "=r"(r[1]) : "r"(addr));
}
__device__ __forceinline__ void mma_bf16(float* c, const uint32_t* a,
                                         const uint32_t* b) {
    asm volatile("mma.sync.aligned.m16n8k16.row.col.f32.bf16.bf16.f32 "
                 "{%0,%1,%2,%3}, {%4,%5,%6,%7}, {%8,%9}, {%0,%1,%2,%3};"
                 : "+f"(c[0]), "+f"(c[1]), "+f"(c[2]), "+f"(c[3])
                 : "r"(a[0]), "r"(a[1]), "r"(a[2]), "r"(a[3]),
                   "r"(b[0]), "r"(b[1]));
}
__device__ __forceinline__ float wredsum(float v) {
    #pragma unroll
    for (int o = 16; o > 0; o >>= 1) v += __shfl_xor_sync(0xffffffffu, v, o);
    return v;
}
__device__ __forceinline__ int wredsumi(int v) {
    #pragma unroll
    for (int o = 16; o > 0; o >>= 1) v += __shfl_xor_sync(0xffffffffu, v, o);
    return v;
}
// hi/lo bf16 split pack: low half = first value
__device__ __forceinline__ void split2(float a, float b, uint32_t &hp, uint32_t &lp) {
    __nv_bfloat16 ha = __float2bfloat16(a);
    __nv_bfloat16 hb = __float2bfloat16(b);
    __nv_bfloat16 la = __float2bfloat16(a - __bfloat162float(ha));
    __nv_bfloat16 lb = __float2bfloat16(b - __bfloat162float(hb));
    hp = (uint32_t)__bfloat16_as_ushort(ha) | ((uint32_t)__bfloat16_as_ushort(hb) << 16);
    lp = (uint32_t)__bfloat16_as_ushort(la) | ((uint32_t)__bfloat16_as_ushort(lb) << 16);
}

// ---------------- merged prep: W images + input planes + degree/rank --------
__global__ void k_prep(const float* __restrict__ Wconv,
                       const float* __restrict__ Wlin,
                       const float* __restrict__ Wpred,
                       const float* __restrict__ x,
                       const int* __restrict__ ei, int e, int n) {
    int i = blockIdx.x * blockDim.x + threadIdx.x;
    if (i < NWP) {
        int l = i >> 14;
        int k = (i >> 7) & 127;
        int nn = i & 127;
        float c = Wconv[l * 16384 + k * 128 + nn];
        float v = Wlin [l * 16384 + k * 128 + nn];
        int pos = nn * SA + k;
        __nv_bfloat16 ch = __float2bfloat16(c);
        __nv_bfloat16 cl = __float2bfloat16(c - __bfloat162float(ch));
        __nv_bfloat16 vh = __float2bfloat16(v);
        __nv_bfloat16 vl = __float2bfloat16(v - __bfloat162float(vh));
        __nv_bfloat16* base = g_wb + (size_t)l * 4 * WIMG;
        base[0 * WIMG + pos] = ch;
        base[1 * WIMG + pos] = cl;
        base[2 * WIMG + pos] = vh;
        base[3 * WIMG + pos] = vl;
    } else if (i < NWTOT) {
        int j = i - NWP;
        int nn = j >> 7;
        int k = j & 127;
        float v = (nn < CC) ? Wpred[k * CC + nn] : 0.f;
        __nv_bfloat16 vh = __float2bfloat16(v);
        __nv_bfloat16 vl = __float2bfloat16(v - __bfloat162float(vh));
        int pos = nn * SA + k;
        g_wbp[pos]         = vh;
        g_wbp[WIMGP + pos] = vl;
    } else if (i < NWTOT + PREPX) {
        int j = i - NWTOT;
        int row = j >> 5;
        float4 v = make_float4(0.f, 0.f, 0.f, 0.f);
        if (row < n) v = ((const float4*)x)[j];
        uint32_t h0, l0, h1, l1;
        split2(v.x, v.y, h0, l0);
        split2(v.z, v.w, h1, l1);
        ((uint2*)g_xh)[j] = make_uint2(h0, h1);
        ((uint2*)g_xl)[j] = make_uint2(l0, l1);
    } else {
        int j = i - NWTOT - PREPX;
        if (j < e) g_rank[j] = atomicAdd(&g_cnt[ei[e + j]], 1);
    }
}

// warp-shuffle block scan; also computes dinv, zeroes g_cnt
__global__ void k_scan1(int n) {
    __shared__ int ws[32];
    int t = threadIdx.x, idx = blockIdx.x * 1024 + t;
    int val = (idx < n) ? g_cnt[idx] : 0;
    if (idx < n) {
        g_dinv[idx] = rsqrtf((float)val + 1.0f);
        g_cnt[idx] = 0;
    }
    int lane = t & 31, w = t >> 5;
    int inc = val;
    #pragma unroll
    for (int o = 1; o < 32; o <<= 1) {
        int u = __shfl_up_sync(0xffffffffu, inc, o);
        if (lane >= o) inc += u;
    }
    if (lane == 31) ws[w] = inc;
    __syncthreads();
    if (w == 0) {
        int s = ws[lane];
        int sc = s;
        #pragma unroll
        for (int o = 1; o < 32; o <<= 1) {
            int u = __shfl_up_sync(0xffffffffu, sc, o);
            if (lane >= o) sc += u;
        }
        ws[lane] = sc - s;
        if (lane == 31) g_part[blockIdx.x] = sc;
    }
    __syncthreads();
    if (idx < n) g_off[idx] = inc - val + ws[w];
}
__global__ void k_scan3(int n, int e) {
    __shared__ int base;
    int t = threadIdx.x;
    if (t < 32) {
        int s = 0;
        for (int j = t; j < blockIdx.x; j += 32) s += g_part[j];
        s = wredsumi(s);
        if (t == 0) base = s;
    }
    __syncthreads();
    int idx = blockIdx.x * 1024 + t;
    if (idx < n) g_off[idx] += base;
    if (blockIdx.x == 0 && t == 0) g_off[n] = e;
}
// atomic-free placement: slot = off[dst] + rank
__global__ void k_place(const int* __restrict__ ei, int e) {
    int i = blockIdx.x * blockDim.x + threadIdx.x;
    if (i < e) {
        int s = ei[i];
        int d = ei[e + i];
        int p = __ldg(&g_off[d]) + g_rank[i];
        g_src[p] = s;
    }
}

// ---------------- tensor-core GEMM: [hc' | hl] = X @ [Wconv | Wlin] ---------
// hc' = dinv-scaled conv product (fp16); hl = lin product (fp16).
// CTA: 128x256, 512 threads.
#define OFF_AL 34816
#define OFF_B  69632
#define MMA_SMEM (OFF_B + 4 * 34816)   // 208896 bytes

__global__ void __launch_bounds__(512, 1)
k_mma(int layer, int nrows) {
    extern __shared__ char smc[];
    uint32_t sb = smem_u32(smc);
    int tid = threadIdx.x;
    int lane = tid & 31;
    int wid = tid >> 5;
    int row0 = blockIdx.x * 128;

    {
        const uint4* src = (const uint4*)(g_wb + (size_t)layer * 4 * WIMG);
        uint4* dst = (uint4*)(smc + OFF_B);
        #pragma unroll
        for (int t = tid; t < 8704; t += 512) dst[t] = src[t];
    }
    {
        const uint4* sh = (const uint4*)g_xh + (size_t)row0 * 16;
        const uint4* sl = (const uint4*)g_xl + (size_t)row0 * 16;
        #pragma unroll
        for (int t = tid; t < 4096; t += 512) {
            int plane = t >> 11, r = (t >> 4) & 127, c = t & 15;
            const uint4* src = plane ? sl : sh;
            *(uint4*)(smc + plane * OFF_AL + r * (SA * 2) + c * 16) = src[r * 16 + c];
        }
    }
    __syncthreads();

    int wr  = wid >> 2;
    int wc2 = wid & 3;
    int sel = wc2 >> 1;
    int nb64 = wc2 & 1;

    int arow = wr * 32 + (lane & 7) + ((lane & 8) ? 8 : 0);
    int akof = (lane & 16) ? 8 : 0;
    uint32_t aH = sb + (uint32_t)(arow * SA + akof) * 2;
    uint32_t aL = aH + OFF_AL;

    int brow = nb64 * 64 + (lane & 7);
    int bkof = (lane & 8) ? 8 : 0;
    uint32_t bH = sb + OFF_B + (uint32_t)sel * 69632 + (uint32_t)(brow * SA + bkof) * 2;
    uint32_t bL = bH + 34816;

    float c[2][8][4];
    #pragma unroll
    for (int i = 0; i < 2; i++)
        #pragma unroll
        for (int j = 0; j < 8; j++)
            #pragma unroll
            for (int q = 0; q < 4; q++) c[i][j][q] = 0.f;

    #pragma unroll
    for (int ks = 0; ks < 8; ks++) {
        uint32_t ka = ks * 32;
        uint32_t ah0[4], ah1[4], al0[4], al1[4];
        ldsm_x4(ah0, aH + ka);
        ldsm_x4(ah1, aH + ka + 16 * SA * 2);
        ldsm_x4(al0, aL + ka);
        ldsm_x4(al1, aL + ka + 16 * SA * 2);
        #pragma unroll
        for (int nt = 0; nt < 8; nt++) {
            uint32_t bh[2], bl[2];
            ldsm_x2(bh, bH + nt * (8 * SA * 2) + ka);
            ldsm_x2(bl, bL + nt * (8 * SA * 2) + ka);
            mma_bf16(c[0][nt], ah0, bh);
            mma_bf16(c[1][nt], ah1, bh);
            mma_bf16(c[0][nt], ah0, bl);
            mma_bf16(c[1][nt], ah1, bl);
            mma_bf16(c[0][nt], al0, bh);
            mma_bf16(c[1][nt], al1, bh);
        }
    }

    int g  = lane >> 2;
    int tg = lane & 3;
    __half* outp = sel ? g_hl : g_hc;
    #pragma unroll
    for (int mt = 0; mt < 2; mt++) {
        int r0 = row0 + wr * 32 + mt * 16 + g;
        float sc0 = 1.f, sc1 = 1.f;
        if (sel == 0) {
            if (r0 < nrows)     sc0 = g_dinv[r0];
            if (r0 + 8 < nrows) sc1 = g_dinv[r0 + 8];
        }
        #pragma unroll
        for (int nt = 0; nt < 8; nt++) {
            int col = nb64 * 64 + nt * 8 + tg * 2;
            if (r0 < nrows) {
                __half2 h = __floats2half2_rn(c[mt][nt][0] * sc0,
                                              c[mt][nt][1] * sc0);
                *(__half2*)(outp + (size_t)r0 * 128 + col) = h;
            }
            if (r0 + 8 < nrows) {
                __half2 h = __floats2half2_rn(c[mt][nt][2] * sc1,
                                              c[mt][nt][3] * sc1);
                *(__half2*)(outp + (size_t)(r0 + 8) * 128 + col) = h;
            }
        }
    }
}

// ---------------- fused aggregate + bias + residual + LN + ReLU + JK --------
// conv = dn * (sum_src HC[src] + HC[node]); HC, HL fp16.
__global__ void __launch_bounds__(256)
k_agg(const float* __restrict__ bconv, const float* __restrict__ blin,
      const float* __restrict__ lng, const float* __restrict__ lnb,
      int layer, int n) {
    int gwarp = (blockIdx.x * blockDim.x + threadIdx.x) >> 5;
    if (gwarp >= n) return;
    int lane = threadIdx.x & 31;
    int node = gwarp;

    float dn = g_dinv[node];
    const uint2* HC2 = (const uint2*)g_hc;   // 4 halfs per lane per row
    const uint2* HL2 = (const uint2*)g_hl;
    const int* S = g_src;

    float4 acc = make_float4(0.f, 0.f, 0.f, 0.f);
    int b = g_off[node], end = g_off[node + 1];
    int i = b;
    #define GATHER(u)                                                          \
        {                                                                      \
            float2 f0 = __half22float2(*(__half2*)&(u).x);                     \
            float2 f1 = __half22float2(*(__half2*)&(u).y);                     \
            acc.x += f0.x; acc.y += f0.y; acc.z += f1.x; acc.w += f1.y;        \
        }
    for (; i + 8 <= end; i += 8) {
        int s0 = S[i],     s1 = S[i + 1], s2 = S[i + 2], s3 = S[i + 3];
        int s4 = S[i + 4], s5 = S[i + 5], s6 = S[i + 6], s7 = S[i + 7];
        uint2 u0 = HC2[s0 * 32 + lane];
        uint2 u1 = HC2[s1 * 32 + lane];
        uint2 u2 = HC2[s2 * 32 + lane];
        uint2 u3 = HC2[s3 * 32 + lane];
        uint2 u4 = HC2[s4 * 32 + lane];
        uint2 u5 = HC2[s5 * 32 + lane];
        uint2 u6 = HC2[s6 * 32 + lane];
        uint2 u7 = HC2[s7 * 32 + lane];
        GATHER(u0) GATHER(u1) GATHER(u2) GATHER(u3)
        GATHER(u4) GATHER(u5) GATHER(u6) GATHER(u7)
    }
    for (; i + 2 <= end; i += 2) {
        uint2 u0 = HC2[S[i] * 32 + lane];
        uint2 u1 = HC2[S[i + 1] * 32 + lane];
        GATHER(u0) GATHER(u1)
    }
    for (; i < end; i++) {
        uint2 u0 = HC2[S[i] * 32 + lane];
        GATHER(u0)
    }
    {
        uint2 us = HC2[node * 32 + lane];    // self loop
        GATHER(us)
    }
    #undef GATHER

    uint2 ul = HL2[node * 32 + lane];
    float2 hl0 = __half22float2(*(__half2*)&ul.x);
    float2 hl1 = __half22float2(*(__half2*)&ul.y);
    float4 bc  = ((const float4*)bconv)[lane];
    float4 bl  = ((const float4*)blin)[lane];
    float v0 = acc.x * dn + bc.x + hl0.x + bl.x;
    float v1 = acc.y * dn + bc.y + hl0.y + bl.y;
    float v2 = acc.z * dn + bc.z + hl1.x + bl.z;
    float v3 = acc.w * dn + bc.w + hl1.y + bl.w;

    float mu = wredsum(v0 + v1 + v2 + v3) * (1.0f / 128.0f);
    float d0 = v0 - mu, d1 = v1 - mu, d2 = v2 - mu, d3 = v3 - mu;
    float var = wredsum(d0 * d0 + d1 * d1 + d2 * d2 + d3 * d3) * (1.0f / 128.0f);
    float inv = rsqrtf(var + EPS);

    float4 g4 = ((const float4*)lng)[lane];
    float4 b4 = ((const float4*)lnb)[lane];
    v0 = fmaxf(0.f, d0 * inv * g4.x + b4.x);
    v1 = fmaxf(0.f, d1 * inv * g4.y + b4.y);
    v2 = fmaxf(0.f, d2 * inv * g4.z + b4.z);
    v3 = fmaxf(0.f, d3 * inv * g4.w + b4.w);

    float s0 = v0, s1 = v1, s2 = v2, s3 = v3;
    float4* XF = (float4*)g_xf;
    if (layer == 0) {
        XF[node * 32 + lane] = make_float4(v0, v1, v2, v3);
    } else {
        float4 r = XF[node * 32 + lane];
        if (layer == 1) {
            r.x += v0; r.y += v1; r.z += v2; r.w += v3;
            XF[node * 32 + lane] = r;
        } else {
            s0 = r.x + v0; s1 = r.y + v1; s2 = r.z + v2; s3 = r.w + v3;
        }
    }

    uint32_t h0, l0, h1, l1;
    split2(s0, s1, h0, l0);
    split2(s2, s3, h1, l1);
    ((uint2*)g_xh)[node * 32 + lane] = make_uint2(h0, h1);
    ((uint2*)g_xl)[node * 32 + lane] = make_uint2(l0, l1);
}

// ---------------- prediction GEMM via mma: out = xf @ Wpred + bpred ---------
#define POFF_AL 34816
#define POFF_B  69632
#define PRED_SMEM (POFF_B + 2 * WIMGP * 2)   // 104448 bytes

__global__ void __launch_bounds__(256, 1)
k_predmma(const float* __restrict__ bp, float* __restrict__ out, int nrows) {
    extern __shared__ char smc[];
    uint32_t sb = smem_u32(smc);
    int tid = threadIdx.x;
    int lane = tid & 31;
    int wid = tid >> 5;
    int row0 = blockIdx.x * 128;

    {
        const uint4* src = (const uint4*)g_wbp;
        uint4* dst = (uint4*)(smc + POFF_B);
        #pragma unroll
        for (int t = tid; t < 2176; t += 256) dst[t] = src[t];
    }
    {
        const uint4* sh = (const uint4*)g_xh + (size_t)row0 * 16;
        const uint4* sl = (const uint4*)g_xl + (size_t)row0 * 16;
        #pragma unroll
        for (int t = tid; t < 4096; t += 256) {
            int plane = t >> 11, r = (t >> 4) & 127, c = t & 15;
            const uint4* src = plane ? sl : sh;
            *(uint4*)(smc + plane * POFF_AL + r * (SA * 2) + c * 16) = src[r * 16 + c];
        }
    }
    __syncthreads();

    int wr = wid >> 1;
    int wc = wid & 1;

    int arow = wr * 32 + (lane & 7) + ((lane & 8) ? 8 : 0);
    int akof = (lane & 16) ? 8 : 0;
    uint32_t aH = sb + (uint32_t)(arow * SA + akof) * 2;
    uint32_t aL = aH + POFF_AL;

    int brow = wc * 32 + (lane & 7);
    int bkof = (lane & 8) ? 8 : 0;
    uint32_t bH = sb + POFF_B + (uint32_t)(brow * SA + bkof) * 2;
    uint32_t bL = bH + WIMGP * 2;

    float c[2][4][4];
    #pragma unroll
    for (int i = 0; i < 2; i++)
        #pragma unroll
        for (int j = 0; j < 4; j++)
            #pragma unroll
            for (int q = 0; q < 4; q++) c[i][j][q] = 0.f;

    #pragma unroll
    for (int ks = 0; ks < 8; ks++) {
        uint32_t ka = ks * 32;
        uint32_t ah0[4], ah1[4], al0[4], al1[4];
        ldsm_x4(ah0, aH + ka);
        ldsm_x4(ah1, aH + ka + 16 * SA * 2);
        ldsm_x4(al0, aL + ka);
        ldsm_x4(al1, aL + ka + 16 * SA * 2);
        #pragma unroll
        for (int nt = 0; nt < 4; nt++) {
            uint32_t bh[2], bl[2];
            ldsm_x2(bh, bH + nt * (8 * SA * 2) + ka);
            ldsm_x2(bl, bL + nt * (8 * SA * 2) + ka);
            mma_bf16(c[0][nt], ah0, bh);
            mma_bf16(c[1][nt], ah1, bh);
            mma_bf16(c[0][nt], ah0, bl);
            mma_bf16(c[1][nt], ah1, bl);
            mma_bf16(c[0][nt], al0, bh);
            mma_bf16(c[1][nt], al1, bh);
        }
    }

    int g  = lane >> 2;
    int tg = lane & 3;
    #pragma unroll
    for (int mt = 0; mt < 2; mt++) {
        int r0 = row0 + wr * 32 + mt * 16 + g;
        #pragma unroll
        for (int nt = 0; nt < 4; nt++) {
            int col = wc * 32 + nt * 8 + tg * 2;
            if (col < CC) {
                float b0 = bp[col], b1 = bp[col + 1];
                if (r0 < nrows)
                    *(float2*)(out + (size_t)r0 * CC + col) =
                        make_float2(c[mt][nt][0] + b0, c[mt][nt][1] + b1);
                if (r0 + 8 < nrows)
                    *(float2*)(out + (size_t)(r0 + 8) * CC + col) =
                        make_float2(c[mt][nt][2] + b0, c[mt][nt][3] + b1);
            }
        }
    }
}

// ---------------- launch ----------------
extern "C" void kernel_launch(void* const* d_in, const int* in_sizes, int n_in,
                              void* d_out, int out_size) {
    const float* x      = (const float*)d_in[0];
    const int*   ei     = (const int*)  d_in[1];
    const float* Wconv  = (const float*)d_in[2];
    const float* bconv  = (const float*)d_in[3];
    const float* Wlin   = (const float*)d_in[4];
    const float* blin   = (const float*)d_in[5];
    const float* ln_g   = (const float*)d_in[6];
    const float* ln_b   = (const float*)d_in[7];
    const float* Wpred  = (const float*)d_in[8];
    const float* bpred  = (const float*)d_in[9];
    float* out = (float*)d_out;

    int n = in_sizes[0] / DD;     // 50000
    int e = in_sizes[1] / 2;      // 600000

    static bool attr_set = false;
    if (!attr_set) {
        cudaFuncSetAttribute(k_mma, cudaFuncAttributeMaxDynamicSharedMemorySize,
                             MMA_SMEM);
        cudaFuncSetAttribute(k_predmma, cudaFuncAttributeMaxDynamicSharedMemorySize,
                             PRED_SMEM);
        attr_set = true;
    }

    int nb = (n + 1023) / 1024;

    k_prep <<<(NWTOT + PREPX + e + 255) / 256, 256>>>(Wconv, Wlin, Wpred, x, ei, e, n);
    k_scan1<<<nb, 1024>>>(n);
    k_scan3<<<nb, 1024>>>(n, e);
    k_place<<<(e + 255) / 256, 256>>>(ei, e);

    int ntiles = (n + 127) / 128;
    for (int i = 0; i < LL; i++) {
        k_mma<<<ntiles, 512, MMA_SMEM>>>(i, n);
        k_agg<<<(n + 7) / 8, 256>>>(bconv + i * HH, blin + i * HH,
                                    ln_g + i * HH, ln_b + i * HH, i, n);
    }

    k_predmma<<<ntiles, 256, PRED_SMEM>>>(bpred, out, n);
}